// round 2
// baseline (speedup 1.0000x reference)
#include <cuda_runtime.h>

// PointPillars pseudo-image: inverse-map + coalesced gather with streaming stores.
// Output: (B=16, C=64, NY=400, NX=400) float32 = 655 MB, fully written each call.

#define B_   16
#define C_   64
#define NY_  400
#define NX_  400
#define PLANE  (NY_ * NX_)      // 160,000 pixels per frame
#define NPIX   (B_ * PLANE)     // 2,560,000 total pixels

// Scratch: pixel -> voxel-row index (-1 = empty). 10.24 MB __device__ global
// (heap allocation is forbidden; static device arrays are the sanctioned scratch).
__device__ int g_map[NPIX];

// ---------------------------------------------------------------------------
// 1) init map to -1 (int4 stores)
// ---------------------------------------------------------------------------
__global__ void init_map_kernel() {
    int i = blockIdx.x * blockDim.x + threadIdx.x;
    if (i < NPIX / 4) {
        reinterpret_cast<int4*>(g_map)[i] = make_int4(-1, -1, -1, -1);
    }
}

// ---------------------------------------------------------------------------
// 2) scatter voxel row ids into the map (unique cells per batch -> no races)
// ---------------------------------------------------------------------------
__global__ void scatter_map_kernel(const int* __restrict__ idx, int n) {
    int i = blockIdx.x * blockDim.x + threadIdx.x;
    if (i < n) {
        int4 v = reinterpret_cast<const int4*>(idx)[i];  // (b, z, y, x)
        g_map[v.x * PLANE + v.z * NX_ + v.w] = i;
    }
}

// ---------------------------------------------------------------------------
// 3) gather: one thread per quad of 4 consecutive x-pixels, 64 channels in
//    chunks of 4. Output stores use .cs (evict-first streaming) — the 655 MB
//    output stream is never re-read and must not thrash L2. Fast path for
//    fully-empty quads (~73%): pure zero-store loop.
// ---------------------------------------------------------------------------
__global__ void __launch_bounds__(256) gather_kernel(
    const float* __restrict__ feat, float* __restrict__ out)
{
    int q = blockIdx.x * blockDim.x + threadIdx.x;   // quad id
    if (q >= NPIX / 4) return;

    int p   = q * 4;                                 // flat pixel index
    int b   = p / PLANE;
    int rem = p - b * PLANE;                         // quad-aligned offset in plane

    int4 m = *reinterpret_cast<const int4*>(g_map + p);

    float* obase = out + (long long)b * C_ * PLANE + rem;
    const float4 zero = make_float4(0.f, 0.f, 0.f, 0.f);

    if ((m.x | m.y | m.z | m.w) < 0 &&
        m.x < 0 && m.y < 0 && m.z < 0 && m.w < 0) {
        // fully empty quad: stream zeros for all channels
#pragma unroll 8
        for (int c = 0; c < C_; ++c) {
            __stcs(reinterpret_cast<float4*>(obase + (long long)c * PLANE), zero);
        }
        return;
    }

    const float* f0 = feat + (long long)m.x * C_;
    const float* f1 = feat + (long long)m.y * C_;
    const float* f2 = feat + (long long)m.z * C_;
    const float* f3 = feat + (long long)m.w * C_;

#pragma unroll 4
    for (int c = 0; c < C_; c += 4) {
        float4 a0 = (m.x >= 0) ? __ldg(reinterpret_cast<const float4*>(f0 + c)) : zero;
        float4 a1 = (m.y >= 0) ? __ldg(reinterpret_cast<const float4*>(f1 + c)) : zero;
        float4 a2 = (m.z >= 0) ? __ldg(reinterpret_cast<const float4*>(f2 + c)) : zero;
        float4 a3 = (m.w >= 0) ? __ldg(reinterpret_cast<const float4*>(f3 + c)) : zero;

        float4 o;
        o.x = a0.x; o.y = a1.x; o.z = a2.x; o.w = a3.x;
        __stcs(reinterpret_cast<float4*>(obase + (long long)(c + 0) * PLANE), o);
        o.x = a0.y; o.y = a1.y; o.z = a2.y; o.w = a3.y;
        __stcs(reinterpret_cast<float4*>(obase + (long long)(c + 1) * PLANE), o);
        o.x = a0.z; o.y = a1.z; o.z = a2.z; o.w = a3.z;
        __stcs(reinterpret_cast<float4*>(obase + (long long)(c + 2) * PLANE), o);
        o.x = a0.w; o.y = a1.w; o.z = a2.w; o.w = a3.w;
        __stcs(reinterpret_cast<float4*>(obase + (long long)(c + 3) * PLANE), o);
    }
}

// ---------------------------------------------------------------------------
// launch
// ---------------------------------------------------------------------------
extern "C" void kernel_launch(void* const* d_in, const int* in_sizes, int n_in,
                              void* d_out, int out_size) {
    const float* feat = (const float*)d_in[0];      // (N, 64) float32
    const int*   idx  = (const int*)d_in[1];        // (N, 4)  int32
    float*       out  = (float*)d_out;              // (16, 64, 400, 400)

    int n_vox = in_sizes[1] / 4;

    init_map_kernel<<<(NPIX / 4 + 255) / 256, 256>>>();
    scatter_map_kernel<<<(n_vox + 255) / 256, 256>>>(idx, n_vox);
    gather_kernel<<<(NPIX / 4 + 255) / 256, 256>>>(feat, out);
}

// round 3
// speedup vs baseline: 2.7270x; 2.7270x over previous
#include <cuda_runtime.h>

// PointPillars pseudo-image: inverse-map (u16) + coalesced gather.
// Output: (B=16, C=64, NY=400, NX=400) float32 = 655 MB, fully written each call.

#define B_   16
#define C_   64
#define NY_  400
#define NX_  400
#define PLANE  (NY_ * NX_)      // 160,000 pixels per frame
#define NPIX   (B_ * PLANE)     // 2,560,000 total pixels

// Scratch: pixel -> (local voxel index + 1), 0 = empty. 5.12 MB __device__ global.
// NV_PER_BATCH (=12000) < 65535 so u16 suffices.
__device__ unsigned short g_map[NPIX];

// ---------------------------------------------------------------------------
// 1) init map to 0 (int4 stores: 8 entries per store)
// ---------------------------------------------------------------------------
__global__ void init_map_kernel() {
    int i = blockIdx.x * blockDim.x + threadIdx.x;
    if (i < NPIX / 8) {
        reinterpret_cast<int4*>(g_map)[i] = make_int4(0, 0, 0, 0);
    }
}

// ---------------------------------------------------------------------------
// 2) scatter local voxel ids (+1) into the map (unique cells -> no races)
// ---------------------------------------------------------------------------
__global__ void scatter_map_kernel(const int* __restrict__ idx, int n, int nvb) {
    int i = blockIdx.x * blockDim.x + threadIdx.x;
    if (i < n) {
        int4 v = reinterpret_cast<const int4*>(idx)[i];  // (b, z, y, x)
        int local = i - v.x * nvb;                       // index within batch
        g_map[v.x * PLANE + v.z * NX_ + v.w] = (unsigned short)(local + 1);
    }
}

// ---------------------------------------------------------------------------
// 3) gather: one thread per quad of 4 consecutive x-pixels, 64 channels in
//    chunks of 4. Predicated loads (no divergent fast path), default stores.
//    Per warp, each channel store covers 128 consecutive x -> 512 B coalesced.
// ---------------------------------------------------------------------------
__global__ void __launch_bounds__(256) gather_kernel(
    const float* __restrict__ feat, float* __restrict__ out, int nvb)
{
    int q = blockIdx.x * blockDim.x + threadIdx.x;   // quad id
    if (q >= NPIX / 4) return;

    int p   = q * 4;                                 // flat pixel index
    int b   = p / PLANE;
    int rem = p - b * PLANE;                         // quad-aligned offset in plane

    ushort4 mv = *reinterpret_cast<const ushort4*>(g_map + p);
    int m0 = (int)mv.x, m1 = (int)mv.y, m2 = (int)mv.z, m3 = (int)mv.w;

    long long base = (long long)b * nvb - 1;         // row = base + m (when m>0)
    const float* f0 = feat + (base + m0) * C_;
    const float* f1 = feat + (base + m1) * C_;
    const float* f2 = feat + (base + m2) * C_;
    const float* f3 = feat + (base + m3) * C_;

    float* obase = out + (long long)b * C_ * PLANE + rem;
    const float4 zero = make_float4(0.f, 0.f, 0.f, 0.f);

#pragma unroll 4
    for (int c = 0; c < C_; c += 4) {
        float4 a0 = (m0 > 0) ? *reinterpret_cast<const float4*>(f0 + c) : zero;
        float4 a1 = (m1 > 0) ? *reinterpret_cast<const float4*>(f1 + c) : zero;
        float4 a2 = (m2 > 0) ? *reinterpret_cast<const float4*>(f2 + c) : zero;
        float4 a3 = (m3 > 0) ? *reinterpret_cast<const float4*>(f3 + c) : zero;

        float4 o;
        o.x = a0.x; o.y = a1.x; o.z = a2.x; o.w = a3.x;
        *reinterpret_cast<float4*>(obase + (long long)(c + 0) * PLANE) = o;
        o.x = a0.y; o.y = a1.y; o.z = a2.y; o.w = a3.y;
        *reinterpret_cast<float4*>(obase + (long long)(c + 1) * PLANE) = o;
        o.x = a0.z; o.y = a1.z; o.z = a2.z; o.w = a3.z;
        *reinterpret_cast<float4*>(obase + (long long)(c + 2) * PLANE) = o;
        o.x = a0.w; o.y = a1.w; o.z = a2.w; o.w = a3.w;
        *reinterpret_cast<float4*>(obase + (long long)(c + 3) * PLANE) = o;
    }
}

// ---------------------------------------------------------------------------
// launch
// ---------------------------------------------------------------------------
extern "C" void kernel_launch(void* const* d_in, const int* in_sizes, int n_in,
                              void* d_out, int out_size) {
    const float* feat = (const float*)d_in[0];      // (N, 64) float32
    const int*   idx  = (const int*)d_in[1];        // (N, 4)  int32
    float*       out  = (float*)d_out;              // (16, 64, 400, 400)

    int n_vox = in_sizes[1] / 4;
    int nvb   = n_vox / B_;                         // voxels per batch frame

    init_map_kernel<<<(NPIX / 8 + 255) / 256, 256>>>();
    scatter_map_kernel<<<(n_vox + 255) / 256, 256>>>(idx, n_vox, nvb);
    gather_kernel<<<(NPIX / 4 + 255) / 256, 256>>>(feat, out, nvb);
}